// round 2
// baseline (speedup 1.0000x reference)
#include <cuda_runtime.h>
#include <math.h>

// ESN recurrence on GB300: persistent kernel, W_res in registers,
// monotonic-counter grid barrier, x broadcast through L2 via out[] rows.
//
// Shapes (fixed per reference):
//   input_data: (2048, 128) f32
//   W_in:       (2048, 128) f32
//   W_res:      (2048, 2048) f32
//   out:        (2048, 2048) f32
//
// out[t] = erf( input[t]@W_in^T[row] + W_res@out[t-1] ) * (1/sqrt(2048))
// (SCALE_IN = SCALE_RES = LEAK = 1)

#define T_STEPS 2048
#define N_RES   2048
#define D_IN    128
#define G_BLOCKS 128
#define ROWS_PER_BLOCK 16          // N_RES / G_BLOCKS
#define THREADS 256
// Per-thread tile: 4 rows x 32 k-values (rowgroup rg = tid/64, kchunk kc = tid%64)

__device__ unsigned int g_counter;

__global__ void esn_reset_kernel() { g_counter = 0u; }

__device__ __forceinline__ unsigned int ld_acquire_gpu(const unsigned int* p) {
    unsigned int v;
    asm volatile("ld.acquire.gpu.global.u32 %0, [%1];" : "=r"(v) : "l"(p) : "memory");
    return v;
}

__global__ void __launch_bounds__(THREADS, 1)
esn_persistent_kernel(const float* __restrict__ input,
                      const float* __restrict__ Win,
                      const float* __restrict__ Wres,
                      float* __restrict__ out)
{
    __shared__ float4 xs4[N_RES / 4];                    // 8 KB: x_{t-1}
    __shared__ float  s_win[ROWS_PER_BLOCK * D_IN];      // 8 KB: W_in slice
    __shared__ float  s_in[D_IN];                        // input row t
    __shared__ float  s_part[32];                        // 8 warps * 4 rows
    __shared__ float  s_u[ROWS_PER_BLOCK];               // U[t][rows]

    const int tid  = threadIdx.x;
    const int rg   = tid >> 6;     // 0..3  (rowgroup: 4 rows each)
    const int kc   = tid & 63;     // 0..63 (k-chunk of 32)
    const int row0 = blockIdx.x * ROWS_PER_BLOCK;

    // ---- one-time: W_in slice to SMEM (rows row0..row0+15 are contiguous) ----
    for (int i = tid; i < ROWS_PER_BLOCK * D_IN; i += THREADS)
        s_win[i] = Win[row0 * D_IN + i];

    // ---- one-time: W_res tile into registers, pre-rotated so that the
    //      per-step SMEM x read  xs4[kc*8 + ((q+kc)&7)]  is bank-conflict-free.
    float4 w4[4][8];
    #pragma unroll
    for (int rr = 0; rr < 4; rr++) {
        const float* wrow = Wres + (size_t)(row0 + rg * 4 + rr) * N_RES + kc * 32;
        #pragma unroll
        for (int q = 0; q < 8; q++) {
            const int qe = (q + kc) & 7;
            w4[rr][q] = *reinterpret_cast<const float4*>(wrow + qe * 4);
        }
    }
    __syncthreads();

    const float inv_sqrt_n = 0.022097086912079608f;  // 1/sqrt(2048)
    const int warp = tid >> 5;
    const int lane = tid & 31;

    for (int t = 0; t < T_STEPS; t++) {
        // ---- stage input row t (x-independent: do before the barrier wait) ----
        if (tid < D_IN / 4) {
            float4 v = __ldcg(reinterpret_cast<const float4*>(input + (size_t)t * D_IN) + tid);
            reinterpret_cast<float4*>(s_in)[tid] = v;
        }
        __syncthreads();

        // ---- U[t][row] = dot(input[t], W_in[row]); 16 threads/row, 8 k each ----
        {
            const int row = tid >> 4;
            const int seg = tid & 15;
            float us = 0.f;
            #pragma unroll
            for (int j = 0; j < 8; j++) {
                const int k = seg * 8 + j;
                us += s_in[k] * s_win[row * D_IN + k];
            }
            #pragma unroll
            for (int off = 8; off; off >>= 1)
                us += __shfl_down_sync(0xffffffffu, us, off, 16);
            if (seg == 0) s_u[row] = us;   // SCALE_IN = 1
        }

        // ---- grid barrier: wait for all blocks to finish step t-1 ----
        if (t > 0) {
            if (tid == 0) {
                const unsigned int target = (unsigned int)t * G_BLOCKS;
                while (ld_acquire_gpu(&g_counter) < target) { }
            }
            __syncthreads();
            // stage x_{t-1} = out[t-1][:] (L2-only loads; freshly produced by peers)
            const float4* xprev = reinterpret_cast<const float4*>(out + (size_t)(t - 1) * N_RES);
            xs4[tid]           = __ldcg(xprev + tid);
            xs4[tid + THREADS] = __ldcg(xprev + tid + THREADS);
        }
        __syncthreads();

        // ---- main dot: acc[rr] = sum_k W[row][k] * x[k] over this thread's 32 k ----
        float acc0 = 0.f, acc1 = 0.f, acc2 = 0.f, acc3 = 0.f;
        if (t > 0) {
            const int base = kc * 8;
            #pragma unroll
            for (int q = 0; q < 8; q++) {
                const float4 xv = xs4[base + ((q + kc) & 7)];
                acc0 = fmaf(w4[0][q].x, xv.x, acc0);
                acc0 = fmaf(w4[0][q].y, xv.y, acc0);
                acc0 = fmaf(w4[0][q].z, xv.z, acc0);
                acc0 = fmaf(w4[0][q].w, xv.w, acc0);
                acc1 = fmaf(w4[1][q].x, xv.x, acc1);
                acc1 = fmaf(w4[1][q].y, xv.y, acc1);
                acc1 = fmaf(w4[1][q].z, xv.z, acc1);
                acc1 = fmaf(w4[1][q].w, xv.w, acc1);
                acc2 = fmaf(w4[2][q].x, xv.x, acc2);
                acc2 = fmaf(w4[2][q].y, xv.y, acc2);
                acc2 = fmaf(w4[2][q].z, xv.z, acc2);
                acc2 = fmaf(w4[2][q].w, xv.w, acc2);
                acc3 = fmaf(w4[3][q].x, xv.x, acc3);
                acc3 = fmaf(w4[3][q].y, xv.y, acc3);
                acc3 = fmaf(w4[3][q].z, xv.z, acc3);
                acc3 = fmaf(w4[3][q].w, xv.w, acc3);
            }
        }

        // ---- reduce across 32 lanes (covers kc within a warp) ----
        #pragma unroll
        for (int off = 16; off; off >>= 1) {
            acc0 += __shfl_xor_sync(0xffffffffu, acc0, off);
            acc1 += __shfl_xor_sync(0xffffffffu, acc1, off);
            acc2 += __shfl_xor_sync(0xffffffffu, acc2, off);
            acc3 += __shfl_xor_sync(0xffffffffu, acc3, off);
        }
        if (lane == 0) {
            s_part[warp * 4 + 0] = acc0;
            s_part[warp * 4 + 1] = acc1;
            s_part[warp * 4 + 2] = acc2;
            s_part[warp * 4 + 3] = acc3;
        }
        __syncthreads();

        // ---- finalize 16 rows: combine the 2 warp-halves, add U, erf, store ----
        if (tid < ROWS_PER_BLOCK) {
            const int rg2 = tid >> 2;
            const int rr  = tid & 3;
            const float sum = s_part[(rg2 * 2 + 0) * 4 + rr] +
                              s_part[(rg2 * 2 + 1) * 4 + rr];
            const float pre = s_u[tid] + sum;   // SCALE_RES = 1
            out[(size_t)t * N_RES + row0 + tid] = erff(pre) * inv_sqrt_n;
        }
        __syncthreads();

        // ---- publish step completion (release) ----
        if (tid == 0) {
            __threadfence();                 // make out[t] row visible gpu-wide
            atomicAdd(&g_counter, 1u);
        }
    }
}

extern "C" void kernel_launch(void* const* d_in, const int* in_sizes, int n_in,
                              void* d_out, int out_size)
{
    const float* input = (const float*)d_in[0];   // (2048, 128)
    const float* Win   = (const float*)d_in[1];   // (2048, 128)
    const float* Wres  = (const float*)d_in[2];   // (2048, 2048)
    float* out = (float*)d_out;                   // (2048, 2048)

    esn_reset_kernel<<<1, 1>>>();
    esn_persistent_kernel<<<G_BLOCKS, THREADS>>>(input, Win, Wres, out);
}